// round 4
// baseline (speedup 1.0000x reference)
#include <cuda_runtime.h>
#include <cstdint>
#include <cstddef>

#define S_LEN 1024
#define E_DIM 512
#define H_DIM 512
#define G3H   1536
#define D_DIM 1024
#define CL    16

// ---------------- device scratch (static allocation only) ----------------
__device__ int   g_tokens[S_LEN];
__device__ float g_gi[(size_t)4 * S_LEN * G3H];   // 25.2 MB, L2-resident
__device__ float g_rep[4 * H_DIM];
__device__ float g_h1[D_DIM];

// ---------------- helpers ----------------
__device__ __forceinline__ float sigf(float x) { return 1.f / (1.f + __expf(-x)); }
__device__ __forceinline__ float tanhf_fast(float x) { return 2.f / (1.f + __expf(-2.f * x)) - 1.f; }

// ---------------- kernel 0: token dtype normalization ----------------
// jnp.int64 may have been demoted to int32 by JAX (x64 disabled). Detect from
// the raw bytes: if interpreted as int64, the high 32-bit word of each value is
// 0 and the low word is a valid token id. Probability of a false int64 verdict
// on real int32 data across 8 probes is ~(1/50257)^8.
__global__ void k_tokens(const void* __restrict__ sent) {
    const int*       p32 = (const int*)sent;
    const long long* p64 = (const long long*)sent;
    bool is64 = true;
#pragma unroll
    for (int k = 0; k < 8; k++) {
        int lo = p32[2 * k], hi = p32[2 * k + 1];
        if (hi != 0 || lo < 0 || lo >= 50257) is64 = false;
    }
    int t = threadIdx.x;
    g_tokens[t] = is64 ? (int)p64[t] : p32[t];
}

// ---------------- kernel 1: gi = x @ Wih^T + bih (+ bhh folded for r,z gates)
// C[M=1024 steps][N=1536 rows], K=512. A rows gathered from emb via tokens
// (reversed sequence for backward GRUs g=1,3). 128x128x8 tile, 256 threads,
// 8x8 microtile.
__global__ __launch_bounds__(256, 2) void k_gemm_gi(
    const float* __restrict__ emb,
    const float* __restrict__ w0, const float* __restrict__ w1,
    const float* __restrict__ w2, const float* __restrict__ w3,
    const float* __restrict__ bi0, const float* __restrict__ bi1,
    const float* __restrict__ bi2, const float* __restrict__ bi3,
    const float* __restrict__ bh0, const float* __restrict__ bh1,
    const float* __restrict__ bh2, const float* __restrict__ bh3)
{
    int g = blockIdx.z;
    const float* Wih = (g == 0) ? w0 : (g == 1) ? w1 : (g == 2) ? w2 : w3;
    const float* bih = (g == 0) ? bi0 : (g == 1) ? bi1 : (g == 2) ? bi2 : bi3;
    const float* bhh = (g == 0) ? bh0 : (g == 1) ? bh1 : (g == 2) ? bh2 : bh3;

    int s0 = blockIdx.y * 128;
    int j0 = blockIdx.x * 128;
    int rev = g & 1;

    __shared__ float As[8][128];
    __shared__ float Bs[8][128];
    __shared__ int   toks[128];

    int tid = threadIdx.x;
    if (tid < 128) {
        int s = s0 + tid;
        toks[tid] = g_tokens[rev ? (S_LEN - 1 - s) : s];
    }
    __syncthreads();

    int tx = tid & 15, ty = tid >> 4;
    float acc[8][8];
#pragma unroll
    for (int i = 0; i < 8; i++)
#pragma unroll
        for (int j = 0; j < 8; j++) acc[i][j] = 0.f;

    int lrow = tid >> 1;
    int kq   = (tid & 1) * 4;
    const float* bptr = Wih + (size_t)(j0 + lrow) * E_DIM + kq;

    for (int kk = 0; kk < E_DIM; kk += 8) {
        float4 av = *(const float4*)(emb + (size_t)toks[lrow] * E_DIM + kk + kq);
        float4 bv = *(const float4*)(bptr + kk);
        As[kq + 0][lrow] = av.x; As[kq + 1][lrow] = av.y;
        As[kq + 2][lrow] = av.z; As[kq + 3][lrow] = av.w;
        Bs[kq + 0][lrow] = bv.x; Bs[kq + 1][lrow] = bv.y;
        Bs[kq + 2][lrow] = bv.z; Bs[kq + 3][lrow] = bv.w;
        __syncthreads();
#pragma unroll
        for (int k = 0; k < 8; k++) {
            float ar[8], br[8];
            *(float4*)&ar[0] = *(const float4*)&As[k][ty * 8];
            *(float4*)&ar[4] = *(const float4*)&As[k][ty * 8 + 4];
            *(float4*)&br[0] = *(const float4*)&Bs[k][tx * 8];
            *(float4*)&br[4] = *(const float4*)&Bs[k][tx * 8 + 4];
#pragma unroll
            for (int i = 0; i < 8; i++)
#pragma unroll
                for (int j = 0; j < 8; j++) acc[i][j] += ar[i] * br[j];
        }
        __syncthreads();
    }

    // epilogue: add bih everywhere; fold bhh for the r,z gates (j < 2H). The
    // n-gate bhh must stay inside r*(...) and is applied in the GRU kernel.
#pragma unroll
    for (int i = 0; i < 8; i++) {
        int s = s0 + ty * 8 + i;
        float* orow = g_gi + ((size_t)g * S_LEN + s) * G3H;
#pragma unroll
        for (int j = 0; j < 8; j++) {
            int jg = j0 + tx * 8 + j;
            float bias = bih[jg] + (jg < 2 * H_DIM ? bhh[jg] : 0.f);
            orow[jg] = acc[i][j] + bias;
        }
    }
}

// ---------------- kernel 2: recurrent GRU, 4 clusters x 16 CTAs -------------
// Cluster rank c owns h-elements [32c, 32c+32) -> 96 Whh rows, held entirely
// in registers (96 floats/thread, 512 threads). Per step: register matvec,
// warp butterfly reduce, gates on warp 0, h broadcast to all 16 CTAs via
// st.shared::cluster into a double-buffered SMEM h, one cluster barrier.
__global__ void __cluster_dims__(CL, 1, 1) __launch_bounds__(512, 1)
k_gru(const float* __restrict__ u0, const float* __restrict__ u1,
      const float* __restrict__ u2, const float* __restrict__ u3,
      const float* __restrict__ bh0, const float* __restrict__ bh1,
      const float* __restrict__ bh2, const float* __restrict__ bh3)
{
    int crank = blockIdx.x & (CL - 1);
    int g     = blockIdx.x / CL;
    const float* Whh = (g == 0) ? u0 : (g == 1) ? u1 : (g == 2) ? u2 : u3;
    const float* bhh = (g == 0) ? bh0 : (g == 1) ? bh1 : (g == 2) ? bh2 : bh3;

    int tid = threadIdx.x, wid = tid >> 5, lane = tid & 31;
    int i_base = crank * 32;

    __shared__ float sh_h[2][H_DIM];
    __shared__ float sh_gh[96];
    __shared__ float sh_bhhn[32];

    // Load this thread's 96 weights: warp wid owns rows fr = wid*6 .. wid*6+5;
    // fr -> gate q = fr>>5, hidden idx = i_base + (fr&31); lane owns columns
    // {lane, 32+lane, ..., 480+lane} so h loads are conflict-free.
    float w[6][16];
    int fr0 = wid * 6;
#pragma unroll
    for (int r = 0; r < 6; r++) {
        int fr   = fr0 + r;
        int grow = (fr >> 5) * H_DIM + i_base + (fr & 31);
        const float* wp = Whh + (size_t)grow * H_DIM + lane;
#pragma unroll
        for (int jj = 0; jj < 16; jj++) w[r][jj] = wp[jj * 32];
    }
    sh_h[0][tid] = 0.f;                       // blockDim == H_DIM
    if (tid < 32) sh_bhhn[tid] = bhh[2 * H_DIM + i_base + tid];
    __syncthreads();
    asm volatile("barrier.cluster.arrive.aligned;" ::: "memory");
    asm volatile("barrier.cluster.wait.aligned;" ::: "memory");

    const float* gi0 = g_gi + (size_t)g * S_LEN * G3H;

    for (int s = 0; s < S_LEN; s++) {
        int cur = s & 1;

        // prefetch gi for this step's epilogue (L2 latency hides under matvec)
        float gir = 0.f, giz = 0.f, gin = 0.f;
        if (wid == 0) {
            const float* gp = gi0 + (size_t)s * G3H + i_base + lane;
            gir = gp[0];
            giz = gp[H_DIM];
            gin = gp[2 * H_DIM];
        }

        float a0 = 0.f, a1 = 0.f, a2 = 0.f, a3 = 0.f, a4 = 0.f, a5 = 0.f;
#pragma unroll
        for (int jj = 0; jj < 16; jj++) {
            float hv = sh_h[cur][jj * 32 + lane];
            a0 += w[0][jj] * hv;
            a1 += w[1][jj] * hv;
            a2 += w[2][jj] * hv;
            a3 += w[3][jj] * hv;
            a4 += w[4][jj] * hv;
            a5 += w[5][jj] * hv;
        }
#pragma unroll
        for (int off = 16; off > 0; off >>= 1) {
            a0 += __shfl_xor_sync(0xffffffffu, a0, off);
            a1 += __shfl_xor_sync(0xffffffffu, a1, off);
            a2 += __shfl_xor_sync(0xffffffffu, a2, off);
            a3 += __shfl_xor_sync(0xffffffffu, a3, off);
            a4 += __shfl_xor_sync(0xffffffffu, a4, off);
            a5 += __shfl_xor_sync(0xffffffffu, a5, off);
        }
        if (lane == 0) {
            sh_gh[fr0 + 0] = a0; sh_gh[fr0 + 1] = a1; sh_gh[fr0 + 2] = a2;
            sh_gh[fr0 + 3] = a3; sh_gh[fr0 + 4] = a4; sh_gh[fr0 + 5] = a5;
        }
        __syncthreads();

        if (wid == 0) {
            float hold = sh_h[cur][i_base + lane];
            float ghr  = sh_gh[lane];          // gate r  (fr = 0*32 + lane)
            float ghz  = sh_gh[32 + lane];     // gate z
            float ghn  = sh_gh[64 + lane];     // gate n (bhh_n applied here)
            float rr = sigf(gir + ghr);
            float zz = sigf(giz + ghz);
            float nn = tanhf_fast(gin + rr * (ghn + sh_bhhn[lane]));
            float hn = (1.f - zz) * nn + zz * hold;

            // broadcast h_new to every CTA's next-buffer slot (incl. self)
            uint32_t laddr;
            asm("{ .reg .u64 t; cvta.to.shared.u64 t, %1; cvt.u32.u64 %0, t; }"
                : "=r"(laddr) : "l"(&sh_h[cur ^ 1][i_base + lane]));
#pragma unroll
            for (int rk = 0; rk < CL; rk++) {
                uint32_t raddr;
                asm("mapa.shared::cluster.u32 %0, %1, %2;"
                    : "=r"(raddr) : "r"(laddr), "r"(rk));
                asm volatile("st.shared::cluster.f32 [%0], %1;"
                             :: "r"(raddr), "f"(hn) : "memory");
            }
            if (s == S_LEN - 1)
                g_rep[g * H_DIM + i_base + lane] = hn;
        }
        // release our stores / acquire peers' stores for the next step
        asm volatile("barrier.cluster.arrive.aligned;" ::: "memory");
        asm volatile("barrier.cluster.wait.aligned;" ::: "memory");
    }
}

// ---------------- kernel 3/4: dense head ----------------
__global__ void k_dense1(const float* __restrict__ w, const float* __restrict__ b) {
    __shared__ float red[128];
    int d = blockIdx.x;
    const float* wr = w + (size_t)d * (4 * H_DIM);
    float s = 0.f;
    for (int k = threadIdx.x; k < 4 * H_DIM; k += 128) s += g_rep[k] * wr[k];
    red[threadIdx.x] = s;
    __syncthreads();
    for (int off = 64; off > 0; off >>= 1) {
        if (threadIdx.x < off) red[threadIdx.x] += red[threadIdx.x + off];
        __syncthreads();
    }
    if (threadIdx.x == 0) g_h1[d] = fmaxf(red[0] + b[d], 0.f);
}

__global__ void k_dense2(const float* __restrict__ w, const float* __restrict__ b,
                         float* __restrict__ out) {
    __shared__ float red[D_DIM];
    int t = threadIdx.x;
    red[t] = g_h1[t] * w[t];
    __syncthreads();
    for (int off = 512; off > 0; off >>= 1) {
        if (t < off) red[t] += red[t + off];
        __syncthreads();
    }
    if (t == 0) out[0] = 1.f / (1.f + __expf(-(red[0] + b[0])));
}

// ---------------- launch ----------------
extern "C" void kernel_launch(void* const* d_in, const int* in_sizes, int n_in,
                              void* d_out, int out_size)
{
    (void)in_sizes; (void)n_in; (void)out_size;
    const void*  sent = d_in[0];
    const float* emb  = (const float*)d_in[1];
    const float *wih[4], *whh[4], *bih[4], *bhh[4];
    for (int g = 0; g < 4; g++) {            // order: ctx_f, ctx_b, qry_f, qry_b
        wih[g] = (const float*)d_in[2 + 4 * g];
        whh[g] = (const float*)d_in[3 + 4 * g];
        bih[g] = (const float*)d_in[4 + 4 * g];
        bhh[g] = (const float*)d_in[5 + 4 * g];
    }
    const float* d1w = (const float*)d_in[18];
    const float* d1b = (const float*)d_in[19];
    const float* d2w = (const float*)d_in[20];
    const float* d2b = (const float*)d_in[21];

    // 16-CTA clusters need the non-portable opt-in (idempotent, not a stream op)
    cudaFuncSetAttribute(k_gru, cudaFuncAttributeNonPortableClusterSizeAllowed, 1);

    k_tokens<<<1, S_LEN>>>(sent);

    dim3 ggrid(G3H / 128, S_LEN / 128, 4);   // (12, 8, 4)
    k_gemm_gi<<<ggrid, 256>>>(emb,
                              wih[0], wih[1], wih[2], wih[3],
                              bih[0], bih[1], bih[2], bih[3],
                              bhh[0], bhh[1], bhh[2], bhh[3]);

    k_gru<<<64, 512>>>(whh[0], whh[1], whh[2], whh[3],
                       bhh[0], bhh[1], bhh[2], bhh[3]);

    k_dense1<<<D_DIM, 128>>>(d1w, d1b);
    k_dense2<<<1, D_DIM>>>(d2w, d2b, (float*)d_out);
}